// round 6
// baseline (speedup 1.0000x reference)
#include <cuda_runtime.h>

#define VOCAB 100000
#define DIM   300
#define ROWBYTES (DIM * 4)   // 1200
#define BATCH 65536
#define KNEG  10
#define NB0   6             // batch 0: rows 0..5 (row 0 = pos)
#define NB1   5             // batch 1: rows 6..10
#define NF4   75            // DIM/4 float4 per row
#define WARPS_PER_BLOCK 8
#define THREADS (WARPS_PER_BLOCK * 32)
#define NBLOCKS (BATCH / WARPS_PER_BLOCK)   // 8192

__device__ float g_partials[NBLOCKS];
__device__ unsigned int g_count;    // zero-init; last block resets after use

__device__ __forceinline__ float softplus_fast(float x) {
    // valid for clipped |x| <= 10
    return __logf(1.0f + __expf(x));
}

__device__ __forceinline__ void prefetch_L2(const char* p) {
    asm volatile("prefetch.global.L2 [%0];" :: "l"(p));
}

__device__ __forceinline__ float dot_partial(const float4& a0, const float4& a1, const float4& a2,
                                             const float4& b0, const float4& b1, const float4& b2) {
    float a = a0.x * b0.x;
    a = fmaf(a0.y, b0.y, a); a = fmaf(a0.z, b0.z, a); a = fmaf(a0.w, b0.w, a);
    float c = a1.x * b1.x;
    c = fmaf(a1.y, b1.y, c); c = fmaf(a1.z, b1.z, c); c = fmaf(a1.w, b1.w, c);
    float e = a2.x * b2.x;
    e = fmaf(a2.y, b2.y, e); e = fmaf(a2.z, b2.z, e); e = fmaf(a2.w, b2.w, e);
    return a + c + e;
}

__global__ __launch_bounds__(THREADS, 6)
void sg_loss_kernel(const float* __restrict__ u_w,
                    const float* __restrict__ v_w,
                    const int*   __restrict__ pos_u,
                    const int*   __restrict__ pos_v,
                    const int*   __restrict__ neg_v,
                    float* __restrict__ out) {
    const int warp = threadIdx.x >> 5;
    const int lane = threadIdx.x & 31;
    const int b = blockIdx.x * WARPS_PER_BLOCK + warp;

    const bool has2 = lane < (NF4 - 64);   // lanes 0..10 hold the 3rd float4

    // negative indices live in lanes 0..9; broadcast on demand
    int nidx = 0;
    if (lane < KNEG) nidx = neg_v[b * KNEG + lane];
    const int pvi = pos_v[b];
    const float* u_row_f = u_w + (long long)pos_u[b] * DIM;

    // ---- fire L2 prefetches for ALL 12 rows (no dest regs => huge DRAM MLP
    // without hurting occupancy). Each 1200B row spans <= 11 lines: lanes 0..9
    // cover 128B-stride points, lane 10 touches the last byte. Never OOB.
    if (lane < 11) {
        const long long off = (lane < 10) ? lane * 128 : (ROWBYTES - 1);
        prefetch_L2(reinterpret_cast<const char*>(u_row_f) + off);
#pragma unroll
        for (int j = 0; j < KNEG + 1; j++) {
            const int idx = (j == 0) ? pvi : __shfl_sync(0x7ffu, nidx, j - 1);
            prefetch_L2(reinterpret_cast<const char*>(v_w + (long long)idx * DIM) + off);
        }
    }

    // ---- gather emb_u (evict-first in L1; single-use data) ----
    const float4* u_row = reinterpret_cast<const float4*>(u_row_f);
    const float4 u0 = __ldcs(u_row + lane);
    const float4 u1 = __ldcs(u_row + lane + 32);
    float4 u2 = make_float4(0.f, 0.f, 0.f, 0.f);
    if (has2) u2 = __ldcs(u_row + lane + 64);

    float lane_loss = 0.f;

    // ================= batch 0: rows 0..5 =================
    {
        float p[NB0];
#pragma unroll
        for (int j = 0; j < NB0; j++) {
            const int idx = (j == 0) ? pvi : __shfl_sync(0xffffffffu, nidx, j - 1);
            const float4* v_row = reinterpret_cast<const float4*>(v_w + (long long)idx * DIM);
            const float4 v0 = __ldcg(v_row + lane);
            const float4 v1 = __ldcg(v_row + lane + 32);
            float4 v2 = make_float4(0.f, 0.f, 0.f, 0.f);
            if (has2) v2 = __ldcg(v_row + lane + 64);
            p[j] = dot_partial(u0, u1, u2, v0, v1, v2);
        }
#pragma unroll
        for (int off = 16; off; off >>= 1)
#pragma unroll
            for (int j = 0; j < NB0; j++)
                p[j] += __shfl_xor_sync(0xffffffffu, p[j], off);

        float sel = 0.f;
#pragma unroll
        for (int j = 0; j < NB0; j++) if (lane == j) sel = p[j];
        if (lane < NB0) {
            float s = fminf(fmaxf(sel, -10.f), 10.f);
            lane_loss += softplus_fast((lane == 0) ? -s : s);
        }
    }

    // ================= batch 1: rows 6..10 =================
    {
        float p[NB1];
#pragma unroll
        for (int j = 0; j < NB1; j++) {
            const int idx = __shfl_sync(0xffffffffu, nidx, NB0 - 1 + j);
            const float4* v_row = reinterpret_cast<const float4*>(v_w + (long long)idx * DIM);
            const float4 v0 = __ldcg(v_row + lane);
            const float4 v1 = __ldcg(v_row + lane + 32);
            float4 v2 = make_float4(0.f, 0.f, 0.f, 0.f);
            if (has2) v2 = __ldcg(v_row + lane + 64);
            p[j] = dot_partial(u0, u1, u2, v0, v1, v2);
        }
#pragma unroll
        for (int off = 16; off; off >>= 1)
#pragma unroll
            for (int j = 0; j < NB1; j++)
                p[j] += __shfl_xor_sync(0xffffffffu, p[j], off);

        float sel = 0.f;
#pragma unroll
        for (int j = 0; j < NB1; j++) if (lane == j) sel = p[j];
        if (lane < NB1) {
            float s = fminf(fmaxf(sel, -10.f), 10.f);
            lane_loss += softplus_fast(s);
        }
    }

    // ---- sum the per-lane losses across the warp ----
#pragma unroll
    for (int off = 16; off; off >>= 1)
        lane_loss += __shfl_xor_sync(0xffffffffu, lane_loss, off);

    __shared__ float sloss[WARPS_PER_BLOCK];
    if (lane == 0) sloss[warp] = lane_loss;
    __syncthreads();

    __shared__ unsigned s_is_last;
    if (threadIdx.x == 0) {
        float t = 0.f;
#pragma unroll
        for (int i = 0; i < WARPS_PER_BLOCK; i++) t += sloss[i];
        g_partials[blockIdx.x] = t;
        __threadfence();
        unsigned prev = atomicAdd(&g_count, 1u);
        s_is_last = (prev == (unsigned)(gridDim.x - 1));
    }
    __syncthreads();

    // ---- last block reduces all partials (deterministic fixed order) ----
    if (s_is_last) {
        __threadfence();
        const float4* pp = reinterpret_cast<const float4*>(g_partials);
        float t = 0.f;
#pragma unroll
        for (int i = 0; i < (NBLOCKS / 4) / THREADS; i++) {   // 8 float4 per thread
            float4 v = pp[threadIdx.x + i * THREADS];
            t += (v.x + v.y) + (v.z + v.w);
        }
#pragma unroll
        for (int off = 16; off; off >>= 1)
            t += __shfl_xor_sync(0xffffffffu, t, off);

        __shared__ float sred[WARPS_PER_BLOCK];
        if (lane == 0) sred[warp] = t;
        __syncthreads();
        if (threadIdx.x == 0) {
            float total = 0.f;
#pragma unroll
            for (int i = 0; i < WARPS_PER_BLOCK; i++) total += sred[i];
            out[0] = total * (1.0f / (float)BATCH);
            g_count = 0;   // reset for next graph replay
        }
    }
}

extern "C" void kernel_launch(void* const* d_in, const int* in_sizes, int n_in,
                              void* d_out, int out_size) {
    const float* u_w   = (const float*)d_in[0];
    const float* v_w   = (const float*)d_in[1];
    const int*   pos_u = (const int*)  d_in[2];
    const int*   pos_v = (const int*)  d_in[3];
    const int*   neg_v = (const int*)  d_in[4];
    float* out = (float*)d_out;

    sg_loss_kernel<<<NBLOCKS, THREADS>>>(u_w, v_w, pos_u, pos_v, neg_v, out);
}

// round 7
// speedup vs baseline: 1.2023x; 1.2023x over previous
#include <cuda_runtime.h>

#define VOCAB 100000
#define DIM   300
#define BATCH 65536
#define KNEG  10
#define NB0   6             // batch 0: rows 0..5 (row 0 = pos)
#define NB1   5             // batch 1: rows 6..10
#define NF4   75            // DIM/4 float4 per row
#define WARPS_PER_BLOCK 8
#define THREADS (WARPS_PER_BLOCK * 32)
#define GRIDB 888                           // 6 blocks/SM x 148 SMs: one wave
#define TOTWARPS (GRIDB * WARPS_PER_BLOCK)  // 7104 persistent warps

__device__ float g_partials[GRIDB];
__device__ unsigned int g_count;    // zero-init; last block resets after use

__device__ __forceinline__ float softplus_fast(float x) {
    // valid for clipped |x| <= 10
    return __logf(1.0f + __expf(x));
}

__device__ __forceinline__ float dot_partial(const float4& a0, const float4& a1, const float4& a2,
                                             const float4& b0, const float4& b1, const float4& b2) {
    float a = a0.x * b0.x;
    a = fmaf(a0.y, b0.y, a); a = fmaf(a0.z, b0.z, a); a = fmaf(a0.w, b0.w, a);
    float c = a1.x * b1.x;
    c = fmaf(a1.y, b1.y, c); c = fmaf(a1.z, b1.z, c); c = fmaf(a1.w, b1.w, c);
    float e = a2.x * b2.x;
    e = fmaf(a2.y, b2.y, e); e = fmaf(a2.z, b2.z, e); e = fmaf(a2.w, b2.w, e);
    return a + c + e;
}

// lanes 0..9 -> neg_v[s*10+lane]; lane 10 -> pos_v[s]; others 0
__device__ __forceinline__ int load_vidx(const int* __restrict__ neg_v,
                                         const int* __restrict__ pos_v,
                                         int s, int lane) {
    int r = 0;
    if (lane < KNEG)       r = neg_v[s * KNEG + lane];
    else if (lane == KNEG) r = pos_v[s];
    return r;
}

__global__ __launch_bounds__(THREADS, 6)
void sg_loss_kernel(const float* __restrict__ u_w,
                    const float* __restrict__ v_w,
                    const int*   __restrict__ pos_u,
                    const int*   __restrict__ pos_v,
                    const int*   __restrict__ neg_v,
                    float* __restrict__ out) {
    const int warp = threadIdx.x >> 5;
    const int lane = threadIdx.x & 31;
    const int gw = blockIdx.x * WARPS_PER_BLOCK + warp;   // persistent warp id

    const bool has2 = lane < (NF4 - 64);   // lanes 0..10 hold the 3rd float4

    float acc = 0.f;        // per-lane loss accumulator across all samples

    int s = gw;
    int vpack = 0, pu = 0;
    if (s < BATCH) {
        vpack = load_vidx(neg_v, pos_v, s, lane);
        pu = pos_u[s];
    }

    while (s < BATCH) {
        const int snext = s + TOTWARPS;

        // ---- gather emb_u (evict-first: single use) ----
        const float4* u_row = reinterpret_cast<const float4*>(u_w + (long long)pu * DIM);
        const float4 u0 = __ldcs(u_row + lane);
        const float4 u1 = __ldcs(u_row + lane + 32);
        float4 u2 = make_float4(0.f, 0.f, 0.f, 0.f);
        if (has2) u2 = __ldcs(u_row + lane + 64);

        // ---- software-pipeline: fetch NEXT sample's indices now ----
        int vpack_n = 0, pu_n = 0;
        if (snext < BATCH) {
            vpack_n = load_vidx(neg_v, pos_v, snext, lane);
            pu_n = pos_u[snext];
        }

        // ================= batch 0: rows 0..5 (row 0 = pos) =================
        {
            float p[NB0];
#pragma unroll
            for (int j = 0; j < NB0; j++) {
                const int idx = __shfl_sync(0xffffffffu, vpack, (j == 0) ? KNEG : (j - 1));
                const float4* v_row = reinterpret_cast<const float4*>(v_w + (long long)idx * DIM);
                const float4 v0 = __ldcg(v_row + lane);
                const float4 v1 = __ldcg(v_row + lane + 32);
                float4 v2 = make_float4(0.f, 0.f, 0.f, 0.f);
                if (has2) v2 = __ldcg(v_row + lane + 64);
                p[j] = dot_partial(u0, u1, u2, v0, v1, v2);
            }
#pragma unroll
            for (int off = 16; off; off >>= 1)
#pragma unroll
                for (int j = 0; j < NB0; j++)
                    p[j] += __shfl_xor_sync(0xffffffffu, p[j], off);

            float sel = 0.f;
#pragma unroll
            for (int j = 0; j < NB0; j++) if (lane == j) sel = p[j];
            if (lane < NB0) {
                float sc = fminf(fmaxf(sel, -10.f), 10.f);
                acc += softplus_fast((lane == 0) ? -sc : sc);
            }
        }

        // ================= batch 1: rows 6..10 =================
        {
            float p[NB1];
#pragma unroll
            for (int j = 0; j < NB1; j++) {
                const int idx = __shfl_sync(0xffffffffu, vpack, NB0 - 1 + j);
                const float4* v_row = reinterpret_cast<const float4*>(v_w + (long long)idx * DIM);
                const float4 v0 = __ldcg(v_row + lane);
                const float4 v1 = __ldcg(v_row + lane + 32);
                float4 v2 = make_float4(0.f, 0.f, 0.f, 0.f);
                if (has2) v2 = __ldcg(v_row + lane + 64);
                p[j] = dot_partial(u0, u1, u2, v0, v1, v2);
            }
#pragma unroll
            for (int off = 16; off; off >>= 1)
#pragma unroll
                for (int j = 0; j < NB1; j++)
                    p[j] += __shfl_xor_sync(0xffffffffu, p[j], off);

            float sel = 0.f;
#pragma unroll
            for (int j = 0; j < NB1; j++) if (lane == j) sel = p[j];
            if (lane < NB1) {
                float sc = fminf(fmaxf(sel, -10.f), 10.f);
                acc += softplus_fast(sc);
            }
        }

        s = snext; vpack = vpack_n; pu = pu_n;
    }

    // ---- one final warp reduction over the per-lane accumulators ----
#pragma unroll
    for (int off = 16; off; off >>= 1)
        acc += __shfl_xor_sync(0xffffffffu, acc, off);

    __shared__ float sloss[WARPS_PER_BLOCK];
    if (lane == 0) sloss[warp] = acc;
    __syncthreads();

    __shared__ unsigned s_is_last;
    if (threadIdx.x == 0) {
        float t = 0.f;
#pragma unroll
        for (int i = 0; i < WARPS_PER_BLOCK; i++) t += sloss[i];
        g_partials[blockIdx.x] = t;
        __threadfence();
        unsigned prev = atomicAdd(&g_count, 1u);
        s_is_last = (prev == (unsigned)(gridDim.x - 1));
    }
    __syncthreads();

    // ---- last block reduces all 888 partials (deterministic fixed order) ----
    if (s_is_last) {
        __threadfence();
        float t = 0.f;
        for (int i = threadIdx.x; i < GRIDB; i += THREADS) t += g_partials[i];
#pragma unroll
        for (int off = 16; off; off >>= 1)
            t += __shfl_xor_sync(0xffffffffu, t, off);

        __shared__ float sred[WARPS_PER_BLOCK];
        if (lane == 0) sred[warp] = t;
        __syncthreads();
        if (threadIdx.x == 0) {
            float total = 0.f;
#pragma unroll
            for (int i = 0; i < WARPS_PER_BLOCK; i++) total += sred[i];
            out[0] = total * (1.0f / (float)BATCH);
            g_count = 0;   // reset for next graph replay
        }
    }
}

extern "C" void kernel_launch(void* const* d_in, const int* in_sizes, int n_in,
                              void* d_out, int out_size) {
    const float* u_w   = (const float*)d_in[0];
    const float* v_w   = (const float*)d_in[1];
    const int*   pos_u = (const int*)  d_in[2];
    const int*   pos_v = (const int*)  d_in[3];
    const int*   neg_v = (const int*)  d_in[4];
    float* out = (float*)d_out;

    sg_loss_kernel<<<GRIDB, THREADS>>>(u_w, v_w, pos_u, pos_v, neg_v, out);
}